// round 1
// baseline (speedup 1.0000x reference)
#include <cuda_runtime.h>
#include <math.h>

// ---------------------------------------------------------------------------
// Problem constants
// ---------------------------------------------------------------------------
#define DIM   768
#define NHEAD 12
#define HD    64          // head dim
#define BATCH 8
#define SEQ   1024
#define TOK   (BATCH*SEQ)         // 8192
#define HID   3072
#define S1V   320                 // SD*(HEAD-1) = 64*5
#define S2V   384                 // SD*HEAD     = 64*6
#define EPS   1e-5f
#define SCALE 0.125f              // (768/12)^-0.5 = 1/8

// ---------------------------------------------------------------------------
// Scratch (no cudaMalloc allowed)
// ---------------------------------------------------------------------------
__device__ float g_normx[TOK * DIM];        // 25 MB  (reused for ln1 and ln2 outputs)
__device__ float g_qkv  [TOK * 3 * DIM];    // 75 MB
__device__ float g_y    [TOK * DIM];        // 25 MB  (attention output, pre-proj)
__device__ float g_h    [TOK * HID];        // 100 MB (MLP hidden)

// ---------------------------------------------------------------------------
// Split LayerNorm: segments [0,320), [320,384), [384,768)
// One block per token, 256 threads. Deterministic tree reductions.
// ---------------------------------------------------------------------------
__global__ void __launch_bounds__(256) ln_split_kernel(
    const float* __restrict__ x,
    const float* __restrict__ ga, const float* __restrict__ ba,
    const float* __restrict__ gb, const float* __restrict__ bb,
    const float* __restrict__ gc, const float* __restrict__ bc,
    float* __restrict__ out)
{
    __shared__ float xs[DIM];
    __shared__ float r1[256];
    __shared__ float r2[256];
    __shared__ float st_m[3];
    __shared__ float st_r[3];

    const int row = blockIdx.x;
    const int tid = threadIdx.x;
    const float* xr = x + (size_t)row * DIM;

    for (int i = tid; i < DIM; i += 256) xs[i] = xr[i];
    __syncthreads();

    const int offs[4] = {0, S1V, S2V, DIM};
    for (int s = 0; s < 3; s++) {
        const int lo = offs[s];
        const int len = offs[s + 1] - lo;
        float s1 = 0.f, s2 = 0.f;
        for (int i = tid; i < len; i += 256) {
            float v = xs[lo + i];
            s1 += v; s2 += v * v;
        }
        r1[tid] = s1; r2[tid] = s2;
        __syncthreads();
        for (int stp = 128; stp > 0; stp >>= 1) {
            if (tid < stp) { r1[tid] += r1[tid + stp]; r2[tid] += r2[tid + stp]; }
            __syncthreads();
        }
        if (tid == 0) {
            float m = r1[0] / (float)len;
            float v = r2[0] / (float)len - m * m;
            st_m[s] = m;
            st_r[s] = rsqrtf(v + EPS);
        }
        __syncthreads();
    }

    float* orow = out + (size_t)row * DIM;
    for (int i = tid; i < DIM; i += 256) {
        int s = (i < S1V) ? 0 : ((i < S2V) ? 1 : 2);
        int li = i - offs[s];
        const float* g = (s == 0) ? ga : ((s == 1) ? gb : gc);
        const float* be = (s == 0) ? ba : ((s == 1) ? bb : bc);
        orow[i] = (xs[i] - st_m[s]) * st_r[s] * g[li] + be[li];
    }
}

// ---------------------------------------------------------------------------
// NT GEMM: C[M,N] = A[M,K] @ B[N,K]^T  (+ epilogue)
// 128x128 block tile, K-tile 8, 256 threads, 8x8 per thread.
// EPI: 0 = none, 1 = +bias +residual, 2 = +bias then exact GELU
// ---------------------------------------------------------------------------
template<int EPI>
__global__ void __launch_bounds__(256) gemm_nt(
    const float* __restrict__ A, const float* __restrict__ B,
    const float* __restrict__ bias, const float* __restrict__ res,
    float* __restrict__ C, int M, int N, int K)
{
    __shared__ float As[8][128];
    __shared__ float Bs[8][128];

    const int tid = threadIdx.x;
    const int tx = tid & 15;
    const int ty = tid >> 4;
    const int bm = blockIdx.y;
    const int bn = blockIdx.x;

    const int lr = tid >> 1;          // 0..127  (tile row for loads)
    const int lk = (tid & 1) << 2;    // 0 or 4  (k sub-offset)

    const float* Ap = A + (size_t)(bm * 128 + lr) * K + lk;
    const float* Bp = B + (size_t)(bn * 128 + lr) * K + lk;

    float acc[8][8];
#pragma unroll
    for (int i = 0; i < 8; i++)
#pragma unroll
        for (int j = 0; j < 8; j++) acc[i][j] = 0.f;

    for (int k0 = 0; k0 < K; k0 += 8) {
        float4 av = *(const float4*)(Ap + k0);
        float4 bv = *(const float4*)(Bp + k0);
        __syncthreads();
        As[lk + 0][lr] = av.x; As[lk + 1][lr] = av.y;
        As[lk + 2][lr] = av.z; As[lk + 3][lr] = av.w;
        Bs[lk + 0][lr] = bv.x; Bs[lk + 1][lr] = bv.y;
        Bs[lk + 2][lr] = bv.z; Bs[lk + 3][lr] = bv.w;
        __syncthreads();
#pragma unroll
        for (int kk = 0; kk < 8; kk++) {
            float4 a0 = *(const float4*)&As[kk][ty * 8];
            float4 a1 = *(const float4*)&As[kk][ty * 8 + 4];
            float4 b0 = *(const float4*)&Bs[kk][tx * 8];
            float4 b1 = *(const float4*)&Bs[kk][tx * 8 + 4];
            float a[8] = {a0.x, a0.y, a0.z, a0.w, a1.x, a1.y, a1.z, a1.w};
            float b[8] = {b0.x, b0.y, b0.z, b0.w, b1.x, b1.y, b1.z, b1.w};
#pragma unroll
            for (int i = 0; i < 8; i++)
#pragma unroll
                for (int j = 0; j < 8; j++)
                    acc[i][j] = fmaf(a[i], b[j], acc[i][j]);
        }
    }

#pragma unroll
    for (int i = 0; i < 8; i++) {
        const int gr = bm * 128 + ty * 8 + i;
        const int gc0 = bn * 128 + tx * 8;
        float* Crow = C + (size_t)gr * N + gc0;
#pragma unroll
        for (int j = 0; j < 8; j++) {
            float v = acc[i][j];
            if (EPI == 1) {
                v += bias[gc0 + j] + res[(size_t)gr * N + gc0 + j];
            } else if (EPI == 2) {
                v += bias[gc0 + j];
                v = 0.5f * v * (1.0f + erff(v * 0.70710678118654752f));
            }
            Crow[j] = v;
        }
    }
}

// ---------------------------------------------------------------------------
// Flash-style attention, fp32.
// grid = (SEQ/64, B*H).  Block: 256 threads (16x16), 64 q-rows per block.
// qkv layout: row m = b*SEQ+n, col = s*768 + h*64 + e   (s = 0:q 1:k 2:v)
// Output y[m, h*64 + e].
// smem: qs[64][65], ks[64][65] (aliased with P), vs[64][64]
// ---------------------------------------------------------------------------
#define ATTN_SMEM ((2 * 64 * 65 + 64 * 64) * 4)

__global__ void __launch_bounds__(256) attn_kernel(
    const float* __restrict__ qkv, float* __restrict__ y)
{
    extern __shared__ float sm[];
    float* qs = sm;                  // 64*65
    float* ks = sm + 64 * 65;        // 64*65 (also holds P after S is computed)
    float* vs = sm + 2 * 64 * 65;    // 64*64

    const int tid = threadIdx.x;
    const int tx = tid & 15;
    const int ty = tid >> 4;
    const int n0 = blockIdx.x * 64;
    const int bh = blockIdx.y;
    const int b = bh / NHEAD;
    const int h = bh % NHEAD;

    const float* base = qkv + (size_t)b * SEQ * (3 * DIM) + h * HD;

    // load q tile
    for (int idx = tid; idx < 64 * 16; idx += 256) {
        int r = idx >> 4, c4 = (idx & 15) * 4;
        float4 v = *(const float4*)(base + (size_t)(n0 + r) * (3 * DIM) + c4);
        qs[r * 65 + c4 + 0] = v.x; qs[r * 65 + c4 + 1] = v.y;
        qs[r * 65 + c4 + 2] = v.z; qs[r * 65 + c4 + 3] = v.w;
    }

    float o[4][4];
    float mrow[4], lrow[4];
#pragma unroll
    for (int i = 0; i < 4; i++) {
        mrow[i] = -INFINITY; lrow[i] = 0.f;
#pragma unroll
        for (int c = 0; c < 4; c++) o[i][c] = 0.f;
    }
    __syncthreads();

    for (int kt = 0; kt < SEQ / 64; kt++) {
        // load K, V tiles
        for (int idx = tid; idx < 64 * 16; idx += 256) {
            int r = idx >> 4, c4 = (idx & 15) * 4;
            const float* krow = base + DIM + (size_t)(kt * 64 + r) * (3 * DIM) + c4;
            float4 kv = *(const float4*)krow;
            ks[r * 65 + c4 + 0] = kv.x; ks[r * 65 + c4 + 1] = kv.y;
            ks[r * 65 + c4 + 2] = kv.z; ks[r * 65 + c4 + 3] = kv.w;
            float4 vv = *(const float4*)(krow + DIM);
            *(float4*)(vs + r * 64 + c4) = vv;
        }
        __syncthreads();

        // S = q @ k^T  (each thread 4x4)
        float s[4][4];
#pragma unroll
        for (int i = 0; i < 4; i++)
#pragma unroll
            for (int j = 0; j < 4; j++) s[i][j] = 0.f;

        for (int e = 0; e < HD; e++) {
            float a[4], bb[4];
#pragma unroll
            for (int i = 0; i < 4; i++) a[i] = qs[(ty * 4 + i) * 65 + e];
#pragma unroll
            for (int j = 0; j < 4; j++) bb[j] = ks[(tx * 4 + j) * 65 + e];
#pragma unroll
            for (int i = 0; i < 4; i++)
#pragma unroll
                for (int j = 0; j < 4; j++)
                    s[i][j] = fmaf(a[i], bb[j], s[i][j]);
        }
        __syncthreads();   // everyone done reading ks; safe to overwrite with P

        // online softmax per row
#pragma unroll
        for (int i = 0; i < 4; i++) {
            float mx = -INFINITY;
#pragma unroll
            for (int j = 0; j < 4; j++) {
                s[i][j] *= SCALE;
                mx = fmaxf(mx, s[i][j]);
            }
#pragma unroll
            for (int off = 8; off > 0; off >>= 1)
                mx = fmaxf(mx, __shfl_xor_sync(0xffffffffu, mx, off, 16));
            float mnew = fmaxf(mrow[i], mx);
            float corr = __expf(mrow[i] - mnew);
            float rs = 0.f;
#pragma unroll
            for (int j = 0; j < 4; j++) {
                float p = __expf(s[i][j] - mnew);
                s[i][j] = p;
                rs += p;
            }
#pragma unroll
            for (int off = 8; off > 0; off >>= 1)
                rs += __shfl_xor_sync(0xffffffffu, rs, off, 16);
            lrow[i] = lrow[i] * corr + rs;
#pragma unroll
            for (int c = 0; c < 4; c++) o[i][c] *= corr;
            mrow[i] = mnew;
            // stash P into (aliased) ks
#pragma unroll
            for (int j = 0; j < 4; j++)
                ks[(ty * 4 + i) * 65 + tx * 4 + j] = s[i][j];
        }
        __syncthreads();   // P visible to all

        // O += P @ V
        for (int j = 0; j < 64; j++) {
            float pi[4], vv[4];
#pragma unroll
            for (int i = 0; i < 4; i++) pi[i] = ks[(ty * 4 + i) * 65 + j];
#pragma unroll
            for (int c = 0; c < 4; c++) vv[c] = vs[j * 64 + tx * 4 + c];
#pragma unroll
            for (int i = 0; i < 4; i++)
#pragma unroll
                for (int c = 0; c < 4; c++)
                    o[i][c] = fmaf(pi[i], vv[c], o[i][c]);
        }
        __syncthreads();   // done with ks/vs; next tile may reload
    }

    // write out: y[(b*SEQ + n0+row)*DIM + h*64 + col]
#pragma unroll
    for (int i = 0; i < 4; i++) {
        float inv = 1.0f / lrow[i];
        const int gr = b * SEQ + n0 + ty * 4 + i;
#pragma unroll
        for (int c = 0; c < 4; c++)
            y[(size_t)gr * DIM + h * HD + tx * 4 + c] = o[i][c] * inv;
    }
}

// ---------------------------------------------------------------------------
// Launch
// ---------------------------------------------------------------------------
extern "C" void kernel_launch(void* const* d_in, const int* in_sizes, int n_in,
                              void* d_out, int out_size)
{
    const float* x      = (const float*)d_in[0];
    const float* ln1a_g = (const float*)d_in[1];
    const float* ln1a_b = (const float*)d_in[2];
    const float* ln1b_g = (const float*)d_in[3];
    const float* ln1b_b = (const float*)d_in[4];
    const float* ln1c_g = (const float*)d_in[5];
    const float* ln1c_b = (const float*)d_in[6];
    const float* ln2a_g = (const float*)d_in[7];
    const float* ln2a_b = (const float*)d_in[8];
    const float* ln2b_g = (const float*)d_in[9];
    const float* ln2b_b = (const float*)d_in[10];
    const float* ln2c_g = (const float*)d_in[11];
    const float* ln2c_b = (const float*)d_in[12];
    const float* qkv_w  = (const float*)d_in[13];
    const float* proj_w = (const float*)d_in[14];
    const float* proj_b = (const float*)d_in[15];
    const float* fc1_w  = (const float*)d_in[16];
    const float* fc1_b  = (const float*)d_in[17];
    const float* fc2_w  = (const float*)d_in[18];
    const float* fc2_b  = (const float*)d_in[19];
    float* out = (float*)d_out;

    float *p_normx, *p_qkv, *p_y, *p_h;
    cudaGetSymbolAddress((void**)&p_normx, g_normx);
    cudaGetSymbolAddress((void**)&p_qkv,   g_qkv);
    cudaGetSymbolAddress((void**)&p_y,     g_y);
    cudaGetSymbolAddress((void**)&p_h,     g_h);

    cudaFuncSetAttribute(attn_kernel,
                         cudaFuncAttributeMaxDynamicSharedMemorySize, ATTN_SMEM);

    // 1. norm1 (split LN)
    ln_split_kernel<<<TOK, 256>>>(x, ln1a_g, ln1a_b, ln1b_g, ln1b_b,
                                  ln1c_g, ln1c_b, p_normx);

    // 2. QKV projection: [8192,768] @ [2304,768]^T
    gemm_nt<0><<<dim3(3 * DIM / 128, TOK / 128), 256>>>(
        p_normx, qkv_w, nullptr, nullptr, p_qkv, TOK, 3 * DIM, DIM);

    // 3. attention
    attn_kernel<<<dim3(SEQ / 64, BATCH * NHEAD), 256, ATTN_SMEM>>>(p_qkv, p_y);

    // 4. output projection + bias + residual (x) -> out
    gemm_nt<1><<<dim3(DIM / 128, TOK / 128), 256>>>(
        p_y, proj_w, proj_b, x, out, TOK, DIM, DIM);

    // 5. norm2 (split LN) on out
    ln_split_kernel<<<TOK, 256>>>(out, ln2a_g, ln2a_b, ln2b_g, ln2b_b,
                                  ln2c_g, ln2c_b, p_normx);

    // 6. FC1 + bias + exact GELU
    gemm_nt<2><<<dim3(HID / 128, TOK / 128), 256>>>(
        p_normx, fc1_w, fc1_b, nullptr, p_h, TOK, HID, DIM);

    // 7. FC2 + bias + residual (out) -> out
    gemm_nt<1><<<dim3(DIM / 128, TOK / 128), 256>>>(
        p_h, fc2_w, fc2_b, out, out, TOK, DIM, HID);
}

// round 3
// speedup vs baseline: 1.3656x; 1.3656x over previous
#include <cuda_runtime.h>
#include <math.h>
#include <stdint.h>
#include <mma.h>

using namespace nvcuda;

// ---------------------------------------------------------------------------
// Problem constants
// ---------------------------------------------------------------------------
#define DIM   768
#define NHEAD 12
#define HD    64
#define BATCH 8
#define SEQ   1024
#define TOK   (BATCH*SEQ)
#define HID   3072
#define S1V   320
#define S2V   384
#define EPS   1e-5f
#define SCALE 0.125f

// ---------------------------------------------------------------------------
// Scratch
// ---------------------------------------------------------------------------
__device__ float g_normx[TOK * DIM];
__device__ float g_qkv  [TOK * 3 * DIM];
__device__ float g_y    [TOK * DIM];
__device__ float g_h    [TOK * HID];

// ---------------------------------------------------------------------------
// wmma TF32 NT GEMM: C[M,N] = A[M,K] @ B[N,K]^T  (+ epilogue)
// CTA tile 128x128, K-chunk 32, 256 threads (8 warps), warp tile 32x64.
// EPI: 0=none, 1=+bias+residual, 2=+bias+exact GELU
// ---------------------------------------------------------------------------
#define LDA 36          // 32 k + 4 pad (floats)
#define SCR_LD 20       // 16 + 4 pad

template<int EPI>
__global__ void __launch_bounds__(256, 2) gemm_wmma(
    const float* __restrict__ A, const float* __restrict__ B,
    const float* __restrict__ bias, const float* __restrict__ res,
    float* __restrict__ C, int M, int N, int K)
{
    __shared__ float As[128 * LDA];
    __shared__ float Bs[128 * LDA];
    __shared__ float scratch[8 * 16 * SCR_LD];

    const int tid  = threadIdx.x;
    const int w    = tid >> 5;
    const int lane = tid & 31;
    const int bm = blockIdx.y, bn = blockIdx.x;
    const int wm = w & 3;       // 4 m-slices of 32
    const int wn = w >> 2;      // 2 n-slices of 64

    const float* Abase = A + (size_t)(bm * 128) * K;
    const float* Bbase = B + (size_t)(bn * 128) * K;

    // load indices: 128 rows x 8 float4 per chunk, 4 per thread
    const int lr = tid >> 1;                 // not used; use idx scheme below

    wmma::fragment<wmma::accumulator, 16, 16, 8, float> acc[2][4];
#pragma unroll
    for (int i = 0; i < 2; i++)
#pragma unroll
        for (int j = 0; j < 4; j++)
            wmma::fill_fragment(acc[i][j], 0.0f);

    const int KC = K >> 5;

    float4 ra[4], rb[4];
    // prologue: load chunk 0 into regs
#pragma unroll
    for (int i = 0; i < 4; i++) {
        int idx = tid + i * 256, r = idx >> 3, c = idx & 7;
        ra[i] = *(const float4*)(Abase + (size_t)r * K + c * 4);
        rb[i] = *(const float4*)(Bbase + (size_t)r * K + c * 4);
    }
#pragma unroll
    for (int i = 0; i < 4; i++) {
        int idx = tid + i * 256, r = idx >> 3, c = idx & 7;
        *(float4*)(As + r * LDA + c * 4) = ra[i];
        *(float4*)(Bs + r * LDA + c * 4) = rb[i];
    }
    __syncthreads();

    for (int c = 0; c < KC; c++) {
        const bool pre = (c + 1 < KC);
        if (pre) {
            const int k0 = (c + 1) << 5;
#pragma unroll
            for (int i = 0; i < 4; i++) {
                int idx = tid + i * 256, r = idx >> 3, cc = idx & 7;
                ra[i] = *(const float4*)(Abase + (size_t)r * K + k0 + cc * 4);
                rb[i] = *(const float4*)(Bbase + (size_t)r * K + k0 + cc * 4);
            }
        }

        // compute on current chunk
#pragma unroll
        for (int kk = 0; kk < 32; kk += 8) {
            wmma::fragment<wmma::matrix_a, 16, 16, 8, wmma::precision::tf32,
                           wmma::row_major> af[2];
            wmma::fragment<wmma::matrix_b, 16, 16, 8, wmma::precision::tf32,
                           wmma::col_major> bf[4];
#pragma unroll
            for (int i = 0; i < 2; i++) {
                wmma::load_matrix_sync(af[i], As + (wm * 32 + i * 16) * LDA + kk, LDA);
#pragma unroll
                for (int e = 0; e < af[i].num_elements; e++)
                    af[i].x[e] = wmma::__float_to_tf32(af[i].x[e]);
            }
#pragma unroll
            for (int j = 0; j < 4; j++) {
                wmma::load_matrix_sync(bf[j], Bs + (wn * 64 + j * 16) * LDA + kk, LDA);
#pragma unroll
                for (int e = 0; e < bf[j].num_elements; e++)
                    bf[j].x[e] = wmma::__float_to_tf32(bf[j].x[e]);
            }
#pragma unroll
            for (int i = 0; i < 2; i++)
#pragma unroll
                for (int j = 0; j < 4; j++)
                    wmma::mma_sync(acc[i][j], af[i], bf[j], acc[i][j]);
        }
        __syncthreads();

        if (pre) {
#pragma unroll
            for (int i = 0; i < 4; i++) {
                int idx = tid + i * 256, r = idx >> 3, cc = idx & 7;
                *(float4*)(As + r * LDA + cc * 4) = ra[i];
                *(float4*)(Bs + r * LDA + cc * 4) = rb[i];
            }
            __syncthreads();
        }
    }

    // epilogue: stage each 16x16 fragment through warp-private scratch
    float* scr = scratch + w * 16 * SCR_LD;
#pragma unroll
    for (int i = 0; i < 2; i++) {
#pragma unroll
        for (int j = 0; j < 4; j++) {
            wmma::store_matrix_sync(scr, acc[i][j], SCR_LD, wmma::mem_row_major);
            __syncwarp();
            const int gr0 = bm * 128 + wm * 32 + i * 16;
            const int gc0 = bn * 128 + wn * 64 + j * 16;
#pragma unroll
            for (int e = 0; e < 8; e++) {
                int idx = lane + e * 32;
                int r = idx >> 4, cc = idx & 15;
                float x = scr[r * SCR_LD + cc];
                if (EPI == 1) {
                    x += bias[gc0 + cc] + res[(size_t)(gr0 + r) * N + gc0 + cc];
                } else if (EPI == 2) {
                    x += bias[gc0 + cc];
                    x = 0.5f * x * (1.0f + erff(x * 0.70710678118654752f));
                }
                C[(size_t)(gr0 + r) * N + gc0 + cc] = x;
            }
            __syncwarp();
        }
    }
}

// ---------------------------------------------------------------------------
// Split LayerNorm
// ---------------------------------------------------------------------------
__global__ void __launch_bounds__(256) ln_split_kernel(
    const float* __restrict__ x,
    const float* __restrict__ ga, const float* __restrict__ ba,
    const float* __restrict__ gb, const float* __restrict__ bb,
    const float* __restrict__ gc, const float* __restrict__ bc,
    float* __restrict__ out)
{
    __shared__ float xs[DIM];
    __shared__ float r1[256];
    __shared__ float r2[256];
    __shared__ float st_m[3];
    __shared__ float st_r[3];

    const int row = blockIdx.x;
    const int tid = threadIdx.x;
    const float* xr = x + (size_t)row * DIM;

    for (int i = tid; i < DIM; i += 256) xs[i] = xr[i];
    __syncthreads();

    const int offs[4] = {0, S1V, S2V, DIM};
    for (int s = 0; s < 3; s++) {
        const int lo = offs[s];
        const int len = offs[s + 1] - lo;
        float s1 = 0.f, s2 = 0.f;
        for (int i = tid; i < len; i += 256) {
            float v = xs[lo + i];
            s1 += v; s2 += v * v;
        }
        r1[tid] = s1; r2[tid] = s2;
        __syncthreads();
        for (int stp = 128; stp > 0; stp >>= 1) {
            if (tid < stp) { r1[tid] += r1[tid + stp]; r2[tid] += r2[tid + stp]; }
            __syncthreads();
        }
        if (tid == 0) {
            float m = r1[0] / (float)len;
            float v = r2[0] / (float)len - m * m;
            st_m[s] = m;
            st_r[s] = rsqrtf(v + EPS);
        }
        __syncthreads();
    }

    float* orow = out + (size_t)row * DIM;
    for (int i = tid; i < DIM; i += 256) {
        int s = (i < S1V) ? 0 : ((i < S2V) ? 1 : 2);
        int li = i - offs[s];
        const float* g = (s == 0) ? ga : ((s == 1) ? gb : gc);
        const float* be = (s == 0) ? ba : ((s == 1) ? bb : bc);
        orow[i] = (xs[i] - st_m[s]) * st_r[s] * g[li] + be[li];
    }
}

// ---------------------------------------------------------------------------
// Flash attention fp32 (unchanged)
// ---------------------------------------------------------------------------
#define ATTN_SMEM ((2 * 64 * 65 + 64 * 64) * 4)

__global__ void __launch_bounds__(256) attn_kernel(
    const float* __restrict__ qkv, float* __restrict__ y)
{
    extern __shared__ float sm[];
    float* qs = sm;
    float* ks = sm + 64 * 65;
    float* vs = sm + 2 * 64 * 65;

    const int tid = threadIdx.x;
    const int tx = tid & 15;
    const int ty = tid >> 4;
    const int n0 = blockIdx.x * 64;
    const int bh = blockIdx.y;
    const int b = bh / NHEAD;
    const int h = bh % NHEAD;

    const float* base = qkv + (size_t)b * SEQ * (3 * DIM) + h * HD;

    for (int idx = tid; idx < 64 * 16; idx += 256) {
        int r = idx >> 4, c4 = (idx & 15) * 4;
        float4 v = *(const float4*)(base + (size_t)(n0 + r) * (3 * DIM) + c4);
        qs[r * 65 + c4 + 0] = v.x; qs[r * 65 + c4 + 1] = v.y;
        qs[r * 65 + c4 + 2] = v.z; qs[r * 65 + c4 + 3] = v.w;
    }

    float o[4][4];
    float mrow[4], lrow[4];
#pragma unroll
    for (int i = 0; i < 4; i++) {
        mrow[i] = -INFINITY; lrow[i] = 0.f;
#pragma unroll
        for (int c = 0; c < 4; c++) o[i][c] = 0.f;
    }
    __syncthreads();

    for (int kt = 0; kt < SEQ / 64; kt++) {
        for (int idx = tid; idx < 64 * 16; idx += 256) {
            int r = idx >> 4, c4 = (idx & 15) * 4;
            const float* krow = base + DIM + (size_t)(kt * 64 + r) * (3 * DIM) + c4;
            float4 kv = *(const float4*)krow;
            ks[r * 65 + c4 + 0] = kv.x; ks[r * 65 + c4 + 1] = kv.y;
            ks[r * 65 + c4 + 2] = kv.z; ks[r * 65 + c4 + 3] = kv.w;
            float4 vv = *(const float4*)(krow + DIM);
            *(float4*)(vs + r * 64 + c4) = vv;
        }
        __syncthreads();

        float s[4][4];
#pragma unroll
        for (int i = 0; i < 4; i++)
#pragma unroll
            for (int j = 0; j < 4; j++) s[i][j] = 0.f;

        for (int e = 0; e < HD; e++) {
            float a[4], bb[4];
#pragma unroll
            for (int i = 0; i < 4; i++) a[i] = qs[(ty * 4 + i) * 65 + e];
#pragma unroll
            for (int j = 0; j < 4; j++) bb[j] = ks[(tx * 4 + j) * 65 + e];
#pragma unroll
            for (int i = 0; i < 4; i++)
#pragma unroll
                for (int j = 0; j < 4; j++)
                    s[i][j] = fmaf(a[i], bb[j], s[i][j]);
        }
        __syncthreads();

#pragma unroll
        for (int i = 0; i < 4; i++) {
            float mx = -INFINITY;
#pragma unroll
            for (int j = 0; j < 4; j++) {
                s[i][j] *= SCALE;
                mx = fmaxf(mx, s[i][j]);
            }
#pragma unroll
            for (int off = 8; off > 0; off >>= 1)
                mx = fmaxf(mx, __shfl_xor_sync(0xffffffffu, mx, off, 16));
            float mnew = fmaxf(mrow[i], mx);
            float corr = __expf(mrow[i] - mnew);
            float rs = 0.f;
#pragma unroll
            for (int j = 0; j < 4; j++) {
                float p = __expf(s[i][j] - mnew);
                s[i][j] = p;
                rs += p;
            }
#pragma unroll
            for (int off = 8; off > 0; off >>= 1)
                rs += __shfl_xor_sync(0xffffffffu, rs, off, 16);
            lrow[i] = lrow[i] * corr + rs;
#pragma unroll
            for (int c = 0; c < 4; c++) o[i][c] *= corr;
            mrow[i] = mnew;
#pragma unroll
            for (int j = 0; j < 4; j++)
                ks[(ty * 4 + i) * 65 + tx * 4 + j] = s[i][j];
        }
        __syncthreads();

        for (int j = 0; j < 64; j++) {
            float pi[4], vv[4];
#pragma unroll
            for (int i = 0; i < 4; i++) pi[i] = ks[(ty * 4 + i) * 65 + j];
#pragma unroll
            for (int c = 0; c < 4; c++) vv[c] = vs[j * 64 + tx * 4 + c];
#pragma unroll
            for (int i = 0; i < 4; i++)
#pragma unroll
                for (int c = 0; c < 4; c++)
                    o[i][c] = fmaf(pi[i], vv[c], o[i][c]);
        }
        __syncthreads();
    }

#pragma unroll
    for (int i = 0; i < 4; i++) {
        float inv = 1.0f / lrow[i];
        const int gr = b * SEQ + n0 + ty * 4 + i;
#pragma unroll
        for (int c = 0; c < 4; c++)
            y[(size_t)gr * DIM + h * HD + tx * 4 + c] = o[i][c] * inv;
    }
}

// ---------------------------------------------------------------------------
// Launch
// ---------------------------------------------------------------------------
extern "C" void kernel_launch(void* const* d_in, const int* in_sizes, int n_in,
                              void* d_out, int out_size)
{
    const float* x      = (const float*)d_in[0];
    const float* ln1a_g = (const float*)d_in[1];
    const float* ln1a_b = (const float*)d_in[2];
    const float* ln1b_g = (const float*)d_in[3];
    const float* ln1b_b = (const float*)d_in[4];
    const float* ln1c_g = (const float*)d_in[5];
    const float* ln1c_b = (const float*)d_in[6];
    const float* ln2a_g = (const float*)d_in[7];
    const float* ln2a_b = (const float*)d_in[8];
    const float* ln2b_g = (const float*)d_in[9];
    const float* ln2b_b = (const float*)d_in[10];
    const float* ln2c_g = (const float*)d_in[11];
    const float* ln2c_b = (const float*)d_in[12];
    const float* qkv_w  = (const float*)d_in[13];
    const float* proj_w = (const float*)d_in[14];
    const float* proj_b = (const float*)d_in[15];
    const float* fc1_w  = (const float*)d_in[16];
    const float* fc1_b  = (const float*)d_in[17];
    const float* fc2_w  = (const float*)d_in[18];
    const float* fc2_b  = (const float*)d_in[19];
    float* out = (float*)d_out;

    float *p_normx, *p_qkv, *p_y, *p_h;
    cudaGetSymbolAddress((void**)&p_normx, g_normx);
    cudaGetSymbolAddress((void**)&p_qkv,   g_qkv);
    cudaGetSymbolAddress((void**)&p_y,     g_y);
    cudaGetSymbolAddress((void**)&p_h,     g_h);

    cudaFuncSetAttribute(attn_kernel,
                         cudaFuncAttributeMaxDynamicSharedMemorySize, ATTN_SMEM);

    // 1. norm1
    ln_split_kernel<<<TOK, 256>>>(x, ln1a_g, ln1a_b, ln1b_g, ln1b_b,
                                  ln1c_g, ln1c_b, p_normx);

    // 2. QKV: [8192,768] @ [2304,768]^T
    gemm_wmma<0><<<dim3(3 * DIM / 128, TOK / 128), 256>>>(
        p_normx, qkv_w, nullptr, nullptr, p_qkv, TOK, 3 * DIM, DIM);

    // 3. attention
    attn_kernel<<<dim3(SEQ / 64, BATCH * NHEAD), 256, ATTN_SMEM>>>(p_qkv, p_y);

    // 4. proj + bias + residual(x)
    gemm_wmma<1><<<dim3(DIM / 128, TOK / 128), 256>>>(
        p_y, proj_w, proj_b, x, out, TOK, DIM, DIM);

    // 5. norm2
    ln_split_kernel<<<TOK, 256>>>(out, ln2a_g, ln2a_b, ln2b_g, ln2b_b,
                                  ln2c_g, ln2c_b, p_normx);

    // 6. FC1 + bias + GELU
    gemm_wmma<2><<<dim3(HID / 128, TOK / 128), 256>>>(
        p_normx, fc1_w, fc1_b, nullptr, p_h, TOK, HID, DIM);

    // 7. FC2 + bias + residual(out)
    gemm_wmma<1><<<dim3(DIM / 128, TOK / 128), 256>>>(
        p_h, fc2_w, fc2_b, out, out, TOK, DIM, HID);
}

// round 4
// speedup vs baseline: 1.5594x; 1.1419x over previous
#include <cuda_runtime.h>
#include <math.h>
#include <stdint.h>
#include <mma.h>

using namespace nvcuda;

// ---------------------------------------------------------------------------
// Problem constants
// ---------------------------------------------------------------------------
#define DIM   768
#define NHEAD 12
#define HD    64
#define BATCH 8
#define SEQ   1024
#define TOK   (BATCH*SEQ)
#define HID   3072
#define S1V   320
#define S2V   384
#define EPS   1e-5f
#define SCALE 0.125f

// ---------------------------------------------------------------------------
// Scratch
// ---------------------------------------------------------------------------
__device__ float g_normx[TOK * DIM];
__device__ float g_qkv  [TOK * 3 * DIM];
__device__ float g_y    [TOK * DIM];
__device__ float g_h    [TOK * HID];
// tf32-rounded weight copies
__device__ float g_wq[3 * DIM * DIM];
__device__ float g_wp[DIM * DIM];
__device__ float g_w1[HID * DIM];
__device__ float g_w2[DIM * HID];

// ---------------------------------------------------------------------------
// Weight rounding: fp32 -> tf32(RN) bits stored as fp32
// ---------------------------------------------------------------------------
__global__ void __launch_bounds__(256) round_tf32_kernel(
    const float* __restrict__ src, float* __restrict__ dst, int n4)
{
    int i = blockIdx.x * 256 + threadIdx.x;
    if (i < n4) {
        float4 v = ((const float4*)src)[i];
        v.x = wmma::__float_to_tf32(v.x);
        v.y = wmma::__float_to_tf32(v.y);
        v.z = wmma::__float_to_tf32(v.z);
        v.w = wmma::__float_to_tf32(v.w);
        ((float4*)dst)[i] = v;
    }
}

// ---------------------------------------------------------------------------
// wmma TF32 NT GEMM with 3-stage cp.async pipeline.
// C[M,N] = A[M,K] @ B[N,K]^T (+ epilogue). Inputs are PRE-ROUNDED to tf32.
// CTA tile 128x128, K-chunk 32, 256 threads (8 warps), warp tile 32x64.
// EPI: 0=none, 1=+bias+residual, 2=+bias+exact GELU (output rounded to tf32)
// ---------------------------------------------------------------------------
#define LDA 36
#define STAGE_F (128 * LDA)
#define GEMM_SMEM (3 * 2 * STAGE_F * 4)
#define SCR_LD 20

__device__ __forceinline__ void cp_async16(uint32_t dst, const float* src) {
    asm volatile("cp.async.cg.shared.global [%0], [%1], 16;\n"
                 :: "r"(dst), "l"(src));
}
__device__ __forceinline__ void cp_commit() {
    asm volatile("cp.async.commit_group;\n" ::: "memory");
}
__device__ __forceinline__ void cp_wait2() {
    asm volatile("cp.async.wait_group 2;\n" ::: "memory");
}

template<int EPI>
__global__ void __launch_bounds__(256, 2) gemm_wmma(
    const float* __restrict__ A, const float* __restrict__ B,
    const float* __restrict__ bias, const float* __restrict__ res,
    float* __restrict__ C, int M, int N, int K)
{
    extern __shared__ float smem[];

    const int tid  = threadIdx.x;
    const int w    = tid >> 5;
    const int lane = tid & 31;
    const int bm = blockIdx.y, bn = blockIdx.x;
    const int wm = w & 3;       // 4 m-slices of 32
    const int wn = w >> 2;      // 2 n-slices of 64

    const float* Abase = A + (size_t)(bm * 128) * K;
    const float* Bbase = B + (size_t)(bn * 128) * K;

    const int lr = tid >> 1;    // unused placeholder
    (void)lr;

    // per-thread load coords: 8 x (row, col4) covering A(4) + B(4)
    const int r0 = tid >> 1;                 // unused
    (void)r0;

    const uint32_t smem_u32 =
        (uint32_t)__cvta_generic_to_shared(smem);

    wmma::fragment<wmma::accumulator, 16, 16, 8, float> acc[2][4];
#pragma unroll
    for (int i = 0; i < 2; i++)
#pragma unroll
        for (int j = 0; j < 4; j++)
            wmma::fill_fragment(acc[i][j], 0.0f);

    const int KC = K >> 5;

    // issue chunk c into stage s
    auto issue = [&](int c, int s) {
        const int k0 = c << 5;
        const uint32_t sbase = smem_u32 + (uint32_t)(s * 2 * STAGE_F) * 4u;
#pragma unroll
        for (int i = 0; i < 4; i++) {
            int idx = tid + i * 256, r = idx >> 3, cc = idx & 7;
            cp_async16(sbase + (uint32_t)(r * LDA + cc * 4) * 4u,
                       Abase + (size_t)r * K + k0 + cc * 4);
        }
#pragma unroll
        for (int i = 0; i < 4; i++) {
            int idx = tid + i * 256, r = idx >> 3, cc = idx & 7;
            cp_async16(sbase + (uint32_t)(STAGE_F + r * LDA + cc * 4) * 4u,
                       Bbase + (size_t)r * K + k0 + cc * 4);
        }
    };

    // prefill 3 stages
    issue(0, 0); cp_commit();
    issue(1, 1); cp_commit();
    issue(2, 2); cp_commit();
    cp_wait2();
    __syncthreads();

    int stage = 0;
    for (int c = 0; c < KC; c++) {
        const float* Abuf = smem + stage * 2 * STAGE_F;
        const float* Bbuf = Abuf + STAGE_F;

#pragma unroll
        for (int kk = 0; kk < 32; kk += 8) {
            wmma::fragment<wmma::matrix_a, 16, 16, 8, wmma::precision::tf32,
                           wmma::row_major> af[2];
            wmma::fragment<wmma::matrix_b, 16, 16, 8, wmma::precision::tf32,
                           wmma::col_major> bf[4];
#pragma unroll
            for (int i = 0; i < 2; i++)
                wmma::load_matrix_sync(af[i], Abuf + (wm * 32 + i * 16) * LDA + kk, LDA);
#pragma unroll
            for (int j = 0; j < 4; j++)
                wmma::load_matrix_sync(bf[j], Bbuf + (wn * 64 + j * 16) * LDA + kk, LDA);
#pragma unroll
            for (int i = 0; i < 2; i++)
#pragma unroll
                for (int j = 0; j < 4; j++)
                    wmma::mma_sync(acc[i][j], af[i], bf[j], acc[i][j]);
        }

        __syncthreads();                 // all warps done reading this stage
        if (c + 3 < KC) issue(c + 3, stage);
        cp_commit();                     // commit (possibly empty) group
        cp_wait2();                      // chunk c+1 resident
        __syncthreads();                 // visibility

        stage = (stage + 1) ? (stage == 2 ? 0 : stage + 1) : 0;
    }

    // epilogue: stage fragments through SMEM scratch (reuse stage-0 region)
    float* scr = smem + w * 16 * SCR_LD;
#pragma unroll
    for (int i = 0; i < 2; i++) {
#pragma unroll
        for (int j = 0; j < 4; j++) {
            wmma::store_matrix_sync(scr, acc[i][j], SCR_LD, wmma::mem_row_major);
            __syncwarp();
            const int gr0 = bm * 128 + wm * 32 + i * 16;
            const int gc0 = bn * 128 + wn * 64 + j * 16;
#pragma unroll
            for (int e = 0; e < 8; e++) {
                int idx = lane + e * 32;
                int r = idx >> 4, cc = idx & 15;
                float x = scr[r * SCR_LD + cc];
                if (EPI == 1) {
                    x += bias[gc0 + cc] + res[(size_t)(gr0 + r) * N + gc0 + cc];
                } else if (EPI == 2) {
                    x += bias[gc0 + cc];
                    x = 0.5f * x * (1.0f + erff(x * 0.70710678118654752f));
                    x = wmma::__float_to_tf32(x);   // feeds FC2 GEMM
                }
                C[(size_t)(gr0 + r) * N + gc0 + cc] = x;
            }
            __syncwarp();
        }
    }
}

// ---------------------------------------------------------------------------
// Split LayerNorm (output rounded to tf32 — it feeds GEMM A operands)
// ---------------------------------------------------------------------------
__global__ void __launch_bounds__(256) ln_split_kernel(
    const float* __restrict__ x,
    const float* __restrict__ ga, const float* __restrict__ ba,
    const float* __restrict__ gb, const float* __restrict__ bb,
    const float* __restrict__ gc, const float* __restrict__ bc,
    float* __restrict__ out)
{
    __shared__ float xs[DIM];
    __shared__ float r1[256];
    __shared__ float r2[256];
    __shared__ float st_m[3];
    __shared__ float st_r[3];

    const int row = blockIdx.x;
    const int tid = threadIdx.x;
    const float* xr = x + (size_t)row * DIM;

    for (int i = tid; i < DIM; i += 256) xs[i] = xr[i];
    __syncthreads();

    const int offs[4] = {0, S1V, S2V, DIM};
    for (int s = 0; s < 3; s++) {
        const int lo = offs[s];
        const int len = offs[s + 1] - lo;
        float s1 = 0.f, s2 = 0.f;
        for (int i = tid; i < len; i += 256) {
            float v = xs[lo + i];
            s1 += v; s2 += v * v;
        }
        r1[tid] = s1; r2[tid] = s2;
        __syncthreads();
        for (int stp = 128; stp > 0; stp >>= 1) {
            if (tid < stp) { r1[tid] += r1[tid + stp]; r2[tid] += r2[tid + stp]; }
            __syncthreads();
        }
        if (tid == 0) {
            float m = r1[0] / (float)len;
            float v = r2[0] / (float)len - m * m;
            st_m[s] = m;
            st_r[s] = rsqrtf(v + EPS);
        }
        __syncthreads();
    }

    float* orow = out + (size_t)row * DIM;
    for (int i = tid; i < DIM; i += 256) {
        int s = (i < S1V) ? 0 : ((i < S2V) ? 1 : 2);
        int li = i - offs[s];
        const float* g = (s == 0) ? ga : ((s == 1) ? gb : gc);
        const float* be = (s == 0) ? ba : ((s == 1) ? bb : bc);
        float v = (xs[i] - st_m[s]) * st_r[s] * g[li] + be[li];
        orow[i] = wmma::__float_to_tf32(v);
    }
}

// ---------------------------------------------------------------------------
// Flash attention fp32 (output rounded to tf32 — it feeds proj GEMM)
// ---------------------------------------------------------------------------
#define ATTN_SMEM ((2 * 64 * 65 + 64 * 64) * 4)

__global__ void __launch_bounds__(256) attn_kernel(
    const float* __restrict__ qkv, float* __restrict__ y)
{
    extern __shared__ float sm[];
    float* qs = sm;
    float* ks = sm + 64 * 65;
    float* vs = sm + 2 * 64 * 65;

    const int tid = threadIdx.x;
    const int tx = tid & 15;
    const int ty = tid >> 4;
    const int n0 = blockIdx.x * 64;
    const int bh = blockIdx.y;
    const int b = bh / NHEAD;
    const int h = bh % NHEAD;

    const float* base = qkv + (size_t)b * SEQ * (3 * DIM) + h * HD;

    for (int idx = tid; idx < 64 * 16; idx += 256) {
        int r = idx >> 4, c4 = (idx & 15) * 4;
        float4 v = *(const float4*)(base + (size_t)(n0 + r) * (3 * DIM) + c4);
        qs[r * 65 + c4 + 0] = v.x; qs[r * 65 + c4 + 1] = v.y;
        qs[r * 65 + c4 + 2] = v.z; qs[r * 65 + c4 + 3] = v.w;
    }

    float o[4][4];
    float mrow[4], lrow[4];
#pragma unroll
    for (int i = 0; i < 4; i++) {
        mrow[i] = -INFINITY; lrow[i] = 0.f;
#pragma unroll
        for (int c = 0; c < 4; c++) o[i][c] = 0.f;
    }
    __syncthreads();

    for (int kt = 0; kt < SEQ / 64; kt++) {
        for (int idx = tid; idx < 64 * 16; idx += 256) {
            int r = idx >> 4, c4 = (idx & 15) * 4;
            const float* krow = base + DIM + (size_t)(kt * 64 + r) * (3 * DIM) + c4;
            float4 kv = *(const float4*)krow;
            ks[r * 65 + c4 + 0] = kv.x; ks[r * 65 + c4 + 1] = kv.y;
            ks[r * 65 + c4 + 2] = kv.z; ks[r * 65 + c4 + 3] = kv.w;
            float4 vv = *(const float4*)(krow + DIM);
            *(float4*)(vs + r * 64 + c4) = vv;
        }
        __syncthreads();

        float s[4][4];
#pragma unroll
        for (int i = 0; i < 4; i++)
#pragma unroll
            for (int j = 0; j < 4; j++) s[i][j] = 0.f;

        for (int e = 0; e < HD; e++) {
            float a[4], bb[4];
#pragma unroll
            for (int i = 0; i < 4; i++) a[i] = qs[(ty * 4 + i) * 65 + e];
#pragma unroll
            for (int j = 0; j < 4; j++) bb[j] = ks[(tx * 4 + j) * 65 + e];
#pragma unroll
            for (int i = 0; i < 4; i++)
#pragma unroll
                for (int j = 0; j < 4; j++)
                    s[i][j] = fmaf(a[i], bb[j], s[i][j]);
        }
        __syncthreads();

#pragma unroll
        for (int i = 0; i < 4; i++) {
            float mx = -INFINITY;
#pragma unroll
            for (int j = 0; j < 4; j++) {
                s[i][j] *= SCALE;
                mx = fmaxf(mx, s[i][j]);
            }
#pragma unroll
            for (int off = 8; off > 0; off >>= 1)
                mx = fmaxf(mx, __shfl_xor_sync(0xffffffffu, mx, off, 16));
            float mnew = fmaxf(mrow[i], mx);
            float corr = __expf(mrow[i] - mnew);
            float rs = 0.f;
#pragma unroll
            for (int j = 0; j < 4; j++) {
                float p = __expf(s[i][j] - mnew);
                s[i][j] = p;
                rs += p;
            }
#pragma unroll
            for (int off = 8; off > 0; off >>= 1)
                rs += __shfl_xor_sync(0xffffffffu, rs, off, 16);
            lrow[i] = lrow[i] * corr + rs;
#pragma unroll
            for (int c = 0; c < 4; c++) o[i][c] *= corr;
            mrow[i] = mnew;
#pragma unroll
            for (int j = 0; j < 4; j++)
                ks[(ty * 4 + i) * 65 + tx * 4 + j] = s[i][j];
        }
        __syncthreads();

        for (int j = 0; j < 64; j++) {
            float pi[4], vv[4];
#pragma unroll
            for (int i = 0; i < 4; i++) pi[i] = ks[(ty * 4 + i) * 65 + j];
#pragma unroll
            for (int c = 0; c < 4; c++) vv[c] = vs[j * 64 + tx * 4 + c];
#pragma unroll
            for (int i = 0; i < 4; i++)
#pragma unroll
                for (int c = 0; c < 4; c++)
                    o[i][c] = fmaf(pi[i], vv[c], o[i][c]);
        }
        __syncthreads();
    }

#pragma unroll
    for (int i = 0; i < 4; i++) {
        float inv = 1.0f / lrow[i];
        const int gr = b * SEQ + n0 + ty * 4 + i;
#pragma unroll
        for (int c = 0; c < 4; c++)
            y[(size_t)gr * DIM + h * HD + tx * 4 + c] =
                wmma::__float_to_tf32(o[i][c] * inv);
    }
}

// ---------------------------------------------------------------------------
// Launch
// ---------------------------------------------------------------------------
extern "C" void kernel_launch(void* const* d_in, const int* in_sizes, int n_in,
                              void* d_out, int out_size)
{
    const float* x      = (const float*)d_in[0];
    const float* ln1a_g = (const float*)d_in[1];
    const float* ln1a_b = (const float*)d_in[2];
    const float* ln1b_g = (const float*)d_in[3];
    const float* ln1b_b = (const float*)d_in[4];
    const float* ln1c_g = (const float*)d_in[5];
    const float* ln1c_b = (const float*)d_in[6];
    const float* ln2a_g = (const float*)d_in[7];
    const float* ln2a_b = (const float*)d_in[8];
    const float* ln2b_g = (const float*)d_in[9];
    const float* ln2b_b = (const float*)d_in[10];
    const float* ln2c_g = (const float*)d_in[11];
    const float* ln2c_b = (const float*)d_in[12];
    const float* qkv_w  = (const float*)d_in[13];
    const float* proj_w = (const float*)d_in[14];
    const float* proj_b = (const float*)d_in[15];
    const float* fc1_w  = (const float*)d_in[16];
    const float* fc1_b  = (const float*)d_in[17];
    const float* fc2_w  = (const float*)d_in[18];
    const float* fc2_b  = (const float*)d_in[19];
    float* out = (float*)d_out;

    float *p_normx, *p_qkv, *p_y, *p_h, *p_wq, *p_wp, *p_w1, *p_w2;
    cudaGetSymbolAddress((void**)&p_normx, g_normx);
    cudaGetSymbolAddress((void**)&p_qkv,   g_qkv);
    cudaGetSymbolAddress((void**)&p_y,     g_y);
    cudaGetSymbolAddress((void**)&p_h,     g_h);
    cudaGetSymbolAddress((void**)&p_wq,    g_wq);
    cudaGetSymbolAddress((void**)&p_wp,    g_wp);
    cudaGetSymbolAddress((void**)&p_w1,    g_w1);
    cudaGetSymbolAddress((void**)&p_w2,    g_w2);

    cudaFuncSetAttribute(attn_kernel,
                         cudaFuncAttributeMaxDynamicSharedMemorySize, ATTN_SMEM);
    cudaFuncSetAttribute(gemm_wmma<0>,
                         cudaFuncAttributeMaxDynamicSharedMemorySize, GEMM_SMEM);
    cudaFuncSetAttribute(gemm_wmma<1>,
                         cudaFuncAttributeMaxDynamicSharedMemorySize, GEMM_SMEM);
    cudaFuncSetAttribute(gemm_wmma<2>,
                         cudaFuncAttributeMaxDynamicSharedMemorySize, GEMM_SMEM);

    // 0. round weights to tf32 (RN)
    {
        int n;
        n = 3 * DIM * DIM / 4;
        round_tf32_kernel<<<(n + 255) / 256, 256>>>(qkv_w, p_wq, n);
        n = DIM * DIM / 4;
        round_tf32_kernel<<<(n + 255) / 256, 256>>>(proj_w, p_wp, n);
        n = HID * DIM / 4;
        round_tf32_kernel<<<(n + 255) / 256, 256>>>(fc1_w, p_w1, n);
        n = DIM * HID / 4;
        round_tf32_kernel<<<(n + 255) / 256, 256>>>(fc2_w, p_w2, n);
    }

    // 1. norm1 (rounds its output)
    ln_split_kernel<<<TOK, 256>>>(x, ln1a_g, ln1a_b, ln1b_g, ln1b_b,
                                  ln1c_g, ln1c_b, p_normx);

    // 2. QKV: [8192,768] @ [2304,768]^T (fp32-precision output for attention)
    gemm_wmma<0><<<dim3(3 * DIM / 128, TOK / 128), 256, GEMM_SMEM>>>(
        p_normx, p_wq, nullptr, nullptr, p_qkv, TOK, 3 * DIM, DIM);

    // 3. attention (rounds its output)
    attn_kernel<<<dim3(SEQ / 64, BATCH * NHEAD), 256, ATTN_SMEM>>>(p_qkv, p_y);

    // 4. proj + bias + residual(x)
    gemm_wmma<1><<<dim3(DIM / 128, TOK / 128), 256, GEMM_SMEM>>>(
        p_y, p_wp, proj_b, x, out, TOK, DIM, DIM);

    // 5. norm2 (rounds its output)
    ln_split_kernel<<<TOK, 256>>>(out, ln2a_g, ln2a_b, ln2b_g, ln2b_b,
                                  ln2c_g, ln2c_b, p_normx);

    // 6. FC1 + bias + GELU (rounds its output)
    gemm_wmma<2><<<dim3(HID / 128, TOK / 128), 256, GEMM_SMEM>>>(
        p_normx, p_w1, fc1_b, nullptr, p_h, TOK, HID, DIM);

    // 7. FC2 + bias + residual(out)
    gemm_wmma<1><<<dim3(DIM / 128, TOK / 128), 256, GEMM_SMEM>>>(
        p_h, p_w2, fc2_b, out, out, TOK, DIM, HID);
}

// round 5
// speedup vs baseline: 1.6375x; 1.0501x over previous
#include <cuda_runtime.h>
#include <math.h>
#include <stdint.h>
#include <mma.h>

using namespace nvcuda;

// ---------------------------------------------------------------------------
// Problem constants
// ---------------------------------------------------------------------------
#define DIM   768
#define NHEAD 12
#define HD    64
#define BATCH 8
#define SEQ   1024
#define TOK   (BATCH*SEQ)
#define HID   3072
#define S1V   320
#define S2V   384
#define EPS   1e-5f
#define SCALE 0.125f

// ---------------------------------------------------------------------------
// Scratch
// ---------------------------------------------------------------------------
__device__ float g_normx[TOK * DIM];
__device__ float g_qkv  [TOK * 3 * DIM];
__device__ float g_y    [TOK * DIM];
__device__ float g_h    [TOK * HID];
// tf32-rounded weight copies
__device__ float g_wq[3 * DIM * DIM];
__device__ float g_wp[DIM * DIM];
__device__ float g_w1[HID * DIM];
__device__ float g_w2[DIM * HID];

// ---------------------------------------------------------------------------
// Weight rounding: fp32 -> tf32(RN) bits stored as fp32
// ---------------------------------------------------------------------------
__global__ void __launch_bounds__(256) round_tf32_kernel(
    const float* __restrict__ src, float* __restrict__ dst, int n4)
{
    int i = blockIdx.x * 256 + threadIdx.x;
    if (i < n4) {
        float4 v = ((const float4*)src)[i];
        v.x = wmma::__float_to_tf32(v.x);
        v.y = wmma::__float_to_tf32(v.y);
        v.z = wmma::__float_to_tf32(v.z);
        v.w = wmma::__float_to_tf32(v.w);
        ((float4*)dst)[i] = v;
    }
}

// ---------------------------------------------------------------------------
// wmma TF32 NT GEMM, 3-stage cp.async pipeline, 64x64 warp tiles.
// C[M,N] = A[M,K] @ B[N,K]^T (+ epilogue). Inputs are PRE-ROUNDED to tf32.
// CTA tile 128x128, K-chunk 32, 128 threads (4 warps, 2x2 of 64x64).
// EPI: 0=none, 1=+bias+residual, 2=+bias+exact GELU (output rounded to tf32)
// ---------------------------------------------------------------------------
#define LDA 36
#define STAGE_F (128 * LDA)
#define GEMM_SMEM (3 * 2 * STAGE_F * 4)
#define EPI_LD 68

__device__ __forceinline__ void cp_async16(uint32_t dst, const float* src) {
    asm volatile("cp.async.cg.shared.global [%0], [%1], 16;\n"
                 :: "r"(dst), "l"(src));
}
__device__ __forceinline__ void cp_commit() {
    asm volatile("cp.async.commit_group;\n" ::: "memory");
}
__device__ __forceinline__ void cp_wait2() {
    asm volatile("cp.async.wait_group 2;\n" ::: "memory");
}

template<int EPI>
__global__ void __launch_bounds__(128, 2) gemm_wmma(
    const float* __restrict__ A, const float* __restrict__ B,
    const float* __restrict__ bias, const float* __restrict__ res,
    float* __restrict__ C, int M, int N, int K)
{
    extern __shared__ float smem[];

    const int tid  = threadIdx.x;
    const int w    = tid >> 5;
    const int lane = tid & 31;
    const int bm = blockIdx.y, bn = blockIdx.x;
    const int wm = w & 1;       // 2 m-slices of 64
    const int wn = w >> 1;      // 2 n-slices of 64

    const float* Abase = A + (size_t)(bm * 128) * K;
    const float* Bbase = B + (size_t)(bn * 128) * K;

    const uint32_t smem_u32 = (uint32_t)__cvta_generic_to_shared(smem);

    wmma::fragment<wmma::accumulator, 16, 16, 8, float> acc[4][4];
#pragma unroll
    for (int i = 0; i < 4; i++)
#pragma unroll
        for (int j = 0; j < 4; j++)
            wmma::fill_fragment(acc[i][j], 0.0f);

    const int KC = K >> 5;

    // issue chunk c into stage s: 128 rows x 8 float4 per operand, 128 threads
    auto issue = [&](int c, int s) {
        const int k0 = c << 5;
        const uint32_t sbase = smem_u32 + (uint32_t)(s * 2 * STAGE_F) * 4u;
#pragma unroll
        for (int i = 0; i < 8; i++) {
            int idx = tid + i * 128, r = idx >> 3, cc = idx & 7;
            cp_async16(sbase + (uint32_t)(r * LDA + cc * 4) * 4u,
                       Abase + (size_t)r * K + k0 + cc * 4);
        }
#pragma unroll
        for (int i = 0; i < 8; i++) {
            int idx = tid + i * 128, r = idx >> 3, cc = idx & 7;
            cp_async16(sbase + (uint32_t)(STAGE_F + r * LDA + cc * 4) * 4u,
                       Bbase + (size_t)r * K + k0 + cc * 4);
        }
    };

    issue(0, 0); cp_commit();
    issue(1, 1); cp_commit();
    issue(2, 2); cp_commit();
    cp_wait2();
    __syncthreads();

    int stage = 0;
    for (int c = 0; c < KC; c++) {
        const float* Abuf = smem + stage * 2 * STAGE_F;
        const float* Bbuf = Abuf + STAGE_F;

#pragma unroll
        for (int kk = 0; kk < 32; kk += 8) {
            wmma::fragment<wmma::matrix_a, 16, 16, 8, wmma::precision::tf32,
                           wmma::row_major> af[4];
            wmma::fragment<wmma::matrix_b, 16, 16, 8, wmma::precision::tf32,
                           wmma::col_major> bf[4];
#pragma unroll
            for (int i = 0; i < 4; i++)
                wmma::load_matrix_sync(af[i], Abuf + (wm * 64 + i * 16) * LDA + kk, LDA);
#pragma unroll
            for (int j = 0; j < 4; j++)
                wmma::load_matrix_sync(bf[j], Bbuf + (wn * 64 + j * 16) * LDA + kk, LDA);
#pragma unroll
            for (int i = 0; i < 4; i++)
#pragma unroll
                for (int j = 0; j < 4; j++)
                    wmma::mma_sync(acc[i][j], af[i], bf[j], acc[i][j]);
        }

        __syncthreads();
        if (c + 3 < KC) issue(c + 3, stage);
        cp_commit();
        cp_wait2();
        __syncthreads();

        stage = (stage == 2) ? 0 : stage + 1;
    }

    // ----- epilogue: dump warp's 64x64 tile to SMEM scratch, then float4 IO
    float* scr = smem + w * (64 * EPI_LD);
#pragma unroll
    for (int i = 0; i < 4; i++)
#pragma unroll
        for (int j = 0; j < 4; j++)
            wmma::store_matrix_sync(scr + (i * 16) * EPI_LD + j * 16,
                                    acc[i][j], EPI_LD, wmma::mem_row_major);
    __syncwarp();

    const int gr0 = bm * 128 + wm * 64;
    const int gc0 = bn * 128 + wn * 64;
#pragma unroll
    for (int e = 0; e < 32; e++) {
        int idx = lane + e * 32;           // 1024 float4 per warp tile
        int r = idx >> 4, c4 = (idx & 15) << 2;
        float4 v = *(float4*)(scr + r * EPI_LD + c4);
        const size_t go = (size_t)(gr0 + r) * N + gc0 + c4;
        if (EPI == 1) {
            float4 bv = *(const float4*)(bias + gc0 + c4);
            float4 rv = *(const float4*)(res + go);
            v.x += bv.x + rv.x; v.y += bv.y + rv.y;
            v.z += bv.z + rv.z; v.w += bv.w + rv.w;
        } else if (EPI == 2) {
            float4 bv = *(const float4*)(bias + gc0 + c4);
            v.x += bv.x; v.y += bv.y; v.z += bv.z; v.w += bv.w;
            v.x = wmma::__float_to_tf32(0.5f * v.x * (1.0f + erff(v.x * 0.70710678118654752f)));
            v.y = wmma::__float_to_tf32(0.5f * v.y * (1.0f + erff(v.y * 0.70710678118654752f)));
            v.z = wmma::__float_to_tf32(0.5f * v.z * (1.0f + erff(v.z * 0.70710678118654752f)));
            v.w = wmma::__float_to_tf32(0.5f * v.w * (1.0f + erff(v.w * 0.70710678118654752f)));
        }
        *(float4*)(C + go) = v;
    }
}

// ---------------------------------------------------------------------------
// Split LayerNorm (output rounded to tf32 — feeds GEMM A operands)
// ---------------------------------------------------------------------------
__global__ void __launch_bounds__(256) ln_split_kernel(
    const float* __restrict__ x,
    const float* __restrict__ ga, const float* __restrict__ ba,
    const float* __restrict__ gb, const float* __restrict__ bb,
    const float* __restrict__ gc, const float* __restrict__ bc,
    float* __restrict__ out)
{
    __shared__ float xs[DIM];
    __shared__ float r1[256];
    __shared__ float r2[256];
    __shared__ float st_m[3];
    __shared__ float st_r[3];

    const int row = blockIdx.x;
    const int tid = threadIdx.x;
    const float* xr = x + (size_t)row * DIM;

    for (int i = tid; i < DIM; i += 256) xs[i] = xr[i];
    __syncthreads();

    const int offs[4] = {0, S1V, S2V, DIM};
    for (int s = 0; s < 3; s++) {
        const int lo = offs[s];
        const int len = offs[s + 1] - lo;
        float s1 = 0.f, s2 = 0.f;
        for (int i = tid; i < len; i += 256) {
            float v = xs[lo + i];
            s1 += v; s2 += v * v;
        }
        r1[tid] = s1; r2[tid] = s2;
        __syncthreads();
        for (int stp = 128; stp > 0; stp >>= 1) {
            if (tid < stp) { r1[tid] += r1[tid + stp]; r2[tid] += r2[tid + stp]; }
            __syncthreads();
        }
        if (tid == 0) {
            float m = r1[0] / (float)len;
            float v = r2[0] / (float)len - m * m;
            st_m[s] = m;
            st_r[s] = rsqrtf(v + EPS);
        }
        __syncthreads();
    }

    float* orow = out + (size_t)row * DIM;
    for (int i = tid; i < DIM; i += 256) {
        int s = (i < S1V) ? 0 : ((i < S2V) ? 1 : 2);
        int li = i - offs[s];
        const float* g = (s == 0) ? ga : ((s == 1) ? gb : gc);
        const float* be = (s == 0) ? ba : ((s == 1) ? bb : bc);
        float v = (xs[i] - st_m[s]) * st_r[s] * g[li] + be[li];
        orow[i] = wmma::__float_to_tf32(v);
    }
}

// ---------------------------------------------------------------------------
// Flash attention fp32 (output rounded to tf32 — feeds proj GEMM)
// ---------------------------------------------------------------------------
#define ATTN_SMEM ((2 * 64 * 65 + 64 * 64) * 4)

__global__ void __launch_bounds__(256) attn_kernel(
    const float* __restrict__ qkv, float* __restrict__ y)
{
    extern __shared__ float sm[];
    float* qs = sm;
    float* ks = sm + 64 * 65;
    float* vs = sm + 2 * 64 * 65;

    const int tid = threadIdx.x;
    const int tx = tid & 15;
    const int ty = tid >> 4;
    const int n0 = blockIdx.x * 64;
    const int bh = blockIdx.y;
    const int b = bh / NHEAD;
    const int h = bh % NHEAD;

    const float* base = qkv + (size_t)b * SEQ * (3 * DIM) + h * HD;

    for (int idx = tid; idx < 64 * 16; idx += 256) {
        int r = idx >> 4, c4 = (idx & 15) * 4;
        float4 v = *(const float4*)(base + (size_t)(n0 + r) * (3 * DIM) + c4);
        qs[r * 65 + c4 + 0] = v.x; qs[r * 65 + c4 + 1] = v.y;
        qs[r * 65 + c4 + 2] = v.z; qs[r * 65 + c4 + 3] = v.w;
    }

    float o[4][4];
    float mrow[4], lrow[4];
#pragma unroll
    for (int i = 0; i < 4; i++) {
        mrow[i] = -INFINITY; lrow[i] = 0.f;
#pragma unroll
        for (int c = 0; c < 4; c++) o[i][c] = 0.f;
    }
    __syncthreads();

    for (int kt = 0; kt < SEQ / 64; kt++) {
        for (int idx = tid; idx < 64 * 16; idx += 256) {
            int r = idx >> 4, c4 = (idx & 15) * 4;
            const float* krow = base + DIM + (size_t)(kt * 64 + r) * (3 * DIM) + c4;
            float4 kv = *(const float4*)krow;
            ks[r * 65 + c4 + 0] = kv.x; ks[r * 65 + c4 + 1] = kv.y;
            ks[r * 65 + c4 + 2] = kv.z; ks[r * 65 + c4 + 3] = kv.w;
            float4 vv = *(const float4*)(krow + DIM);
            *(float4*)(vs + r * 64 + c4) = vv;
        }
        __syncthreads();

        float s[4][4];
#pragma unroll
        for (int i = 0; i < 4; i++)
#pragma unroll
            for (int j = 0; j < 4; j++) s[i][j] = 0.f;

        for (int e = 0; e < HD; e++) {
            float a[4], bb[4];
#pragma unroll
            for (int i = 0; i < 4; i++) a[i] = qs[(ty * 4 + i) * 65 + e];
#pragma unroll
            for (int j = 0; j < 4; j++) bb[j] = ks[(tx * 4 + j) * 65 + e];
#pragma unroll
            for (int i = 0; i < 4; i++)
#pragma unroll
                for (int j = 0; j < 4; j++)
                    s[i][j] = fmaf(a[i], bb[j], s[i][j]);
        }
        __syncthreads();

#pragma unroll
        for (int i = 0; i < 4; i++) {
            float mx = -INFINITY;
#pragma unroll
            for (int j = 0; j < 4; j++) {
                s[i][j] *= SCALE;
                mx = fmaxf(mx, s[i][j]);
            }
#pragma unroll
            for (int off = 8; off > 0; off >>= 1)
                mx = fmaxf(mx, __shfl_xor_sync(0xffffffffu, mx, off, 16));
            float mnew = fmaxf(mrow[i], mx);
            float corr = __expf(mrow[i] - mnew);
            float rs = 0.f;
#pragma unroll
            for (int j = 0; j < 4; j++) {
                float p = __expf(s[i][j] - mnew);
                s[i][j] = p;
                rs += p;
            }
#pragma unroll
            for (int off = 8; off > 0; off >>= 1)
                rs += __shfl_xor_sync(0xffffffffu, rs, off, 16);
            lrow[i] = lrow[i] * corr + rs;
#pragma unroll
            for (int c = 0; c < 4; c++) o[i][c] *= corr;
            mrow[i] = mnew;
#pragma unroll
            for (int j = 0; j < 4; j++)
                ks[(ty * 4 + i) * 65 + tx * 4 + j] = s[i][j];
        }
        __syncthreads();

        for (int j = 0; j < 64; j++) {
            float pi[4], vv[4];
#pragma unroll
            for (int i = 0; i < 4; i++) pi[i] = ks[(ty * 4 + i) * 65 + j];
#pragma unroll
            for (int c = 0; c < 4; c++) vv[c] = vs[j * 64 + tx * 4 + c];
#pragma unroll
            for (int i = 0; i < 4; i++)
#pragma unroll
                for (int c = 0; c < 4; c++)
                    o[i][c] = fmaf(pi[i], vv[c], o[i][c]);
        }
        __syncthreads();
    }

#pragma unroll
    for (int i = 0; i < 4; i++) {
        float inv = 1.0f / lrow[i];
        const int gr = b * SEQ + n0 + ty * 4 + i;
#pragma unroll
        for (int c = 0; c < 4; c++)
            y[(size_t)gr * DIM + h * HD + tx * 4 + c] =
                wmma::__float_to_tf32(o[i][c] * inv);
    }
}

// ---------------------------------------------------------------------------
// Launch
// ---------------------------------------------------------------------------
extern "C" void kernel_launch(void* const* d_in, const int* in_sizes, int n_in,
                              void* d_out, int out_size)
{
    const float* x      = (const float*)d_in[0];
    const float* ln1a_g = (const float*)d_in[1];
    const float* ln1a_b = (const float*)d_in[2];
    const float* ln1b_g = (const float*)d_in[3];
    const float* ln1b_b = (const float*)d_in[4];
    const float* ln1c_g = (const float*)d_in[5];
    const float* ln1c_b = (const float*)d_in[6];
    const float* ln2a_g = (const float*)d_in[7];
    const float* ln2a_b = (const float*)d_in[8];
    const float* ln2b_g = (const float*)d_in[9];
    const float* ln2b_b = (const float*)d_in[10];
    const float* ln2c_g = (const float*)d_in[11];
    const float* ln2c_b = (const float*)d_in[12];
    const float* qkv_w  = (const float*)d_in[13];
    const float* proj_w = (const float*)d_in[14];
    const float* proj_b = (const float*)d_in[15];
    const float* fc1_w  = (const float*)d_in[16];
    const float* fc1_b  = (const float*)d_in[17];
    const float* fc2_w  = (const float*)d_in[18];
    const float* fc2_b  = (const float*)d_in[19];
    float* out = (float*)d_out;

    float *p_normx, *p_qkv, *p_y, *p_h, *p_wq, *p_wp, *p_w1, *p_w2;
    cudaGetSymbolAddress((void**)&p_normx, g_normx);
    cudaGetSymbolAddress((void**)&p_qkv,   g_qkv);
    cudaGetSymbolAddress((void**)&p_y,     g_y);
    cudaGetSymbolAddress((void**)&p_h,     g_h);
    cudaGetSymbolAddress((void**)&p_wq,    g_wq);
    cudaGetSymbolAddress((void**)&p_wp,    g_wp);
    cudaGetSymbolAddress((void**)&p_w1,    g_w1);
    cudaGetSymbolAddress((void**)&p_w2,    g_w2);

    cudaFuncSetAttribute(attn_kernel,
                         cudaFuncAttributeMaxDynamicSharedMemorySize, ATTN_SMEM);
    cudaFuncSetAttribute(gemm_wmma<0>,
                         cudaFuncAttributeMaxDynamicSharedMemorySize, GEMM_SMEM);
    cudaFuncSetAttribute(gemm_wmma<1>,
                         cudaFuncAttributeMaxDynamicSharedMemorySize, GEMM_SMEM);
    cudaFuncSetAttribute(gemm_wmma<2>,
                         cudaFuncAttributeMaxDynamicSharedMemorySize, GEMM_SMEM);

    // 0. round weights to tf32 (RN)
    {
        int n;
        n = 3 * DIM * DIM / 4;
        round_tf32_kernel<<<(n + 255) / 256, 256>>>(qkv_w, p_wq, n);
        n = DIM * DIM / 4;
        round_tf32_kernel<<<(n + 255) / 256, 256>>>(proj_w, p_wp, n);
        n = HID * DIM / 4;
        round_tf32_kernel<<<(n + 255) / 256, 256>>>(fc1_w, p_w1, n);
        n = DIM * HID / 4;
        round_tf32_kernel<<<(n + 255) / 256, 256>>>(fc2_w, p_w2, n);
    }

    // 1. norm1
    ln_split_kernel<<<TOK, 256>>>(x, ln1a_g, ln1a_b, ln1b_g, ln1b_b,
                                  ln1c_g, ln1c_b, p_normx);

    // 2. QKV
    gemm_wmma<0><<<dim3(3 * DIM / 128, TOK / 128), 128, GEMM_SMEM>>>(
        p_normx, p_wq, nullptr, nullptr, p_qkv, TOK, 3 * DIM, DIM);

    // 3. attention
    attn_kernel<<<dim3(SEQ / 64, BATCH * NHEAD), 256, ATTN_SMEM>>>(p_qkv, p_y);

    // 4. proj + bias + residual(x)
    gemm_wmma<1><<<dim3(DIM / 128, TOK / 128), 128, GEMM_SMEM>>>(
        p_y, p_wp, proj_b, x, out, TOK, DIM, DIM);

    // 5. norm2
    ln_split_kernel<<<TOK, 256>>>(out, ln2a_g, ln2a_b, ln2b_g, ln2b_b,
                                  ln2c_g, ln2c_b, p_normx);

    // 6. FC1 + bias + GELU
    gemm_wmma<2><<<dim3(HID / 128, TOK / 128), 128, GEMM_SMEM>>>(
        p_normx, p_w1, fc1_b, nullptr, p_h, TOK, HID, DIM);

    // 7. FC2 + bias + residual(out)
    gemm_wmma<1><<<dim3(DIM / 128, TOK / 128), 128, GEMM_SMEM>>>(
        p_h, p_w2, fc2_b, out, out, TOK, DIM, HID);
}

// round 6
// speedup vs baseline: 2.1763x; 1.3290x over previous
#include <cuda_runtime.h>
#include <math.h>
#include <stdint.h>
#include <mma.h>

using namespace nvcuda;

// ---------------------------------------------------------------------------
// Problem constants
// ---------------------------------------------------------------------------
#define DIM   768
#define NHEAD 12
#define HD    64
#define BATCH 8
#define SEQ   1024
#define TOK   (BATCH*SEQ)
#define HID   3072
#define S1V   320
#define S2V   384
#define EPS   1e-5f
#define SCALE 0.125f

// ---------------------------------------------------------------------------
// Scratch
// ---------------------------------------------------------------------------
__device__ float g_normx[TOK * DIM];
__device__ float g_qkv  [TOK * 3 * DIM];
__device__ float g_y    [TOK * DIM];
__device__ float g_h    [TOK * HID];
__device__ float g_wq[3 * DIM * DIM];
__device__ float g_wp[DIM * DIM];
__device__ float g_w1[HID * DIM];
__device__ float g_w2[DIM * HID];

// ---------------------------------------------------------------------------
// Weight rounding: fp32 -> tf32(RN)
// ---------------------------------------------------------------------------
__global__ void __launch_bounds__(256) round_tf32_kernel(
    const float* __restrict__ src, float* __restrict__ dst, int n4)
{
    int i = blockIdx.x * 256 + threadIdx.x;
    if (i < n4) {
        float4 v = ((const float4*)src)[i];
        v.x = wmma::__float_to_tf32(v.x);
        v.y = wmma::__float_to_tf32(v.y);
        v.z = wmma::__float_to_tf32(v.z);
        v.w = wmma::__float_to_tf32(v.w);
        ((float4*)dst)[i] = v;
    }
}

// ---------------------------------------------------------------------------
// wmma TF32 NT GEMM (unchanged from R5): 3-stage cp.async, 64x64 warp tiles
// ---------------------------------------------------------------------------
#define LDA 36
#define STAGE_F (128 * LDA)
#define GEMM_SMEM (3 * 2 * STAGE_F * 4)
#define EPI_LD 68

__device__ __forceinline__ void cp_async16(uint32_t dst, const float* src) {
    asm volatile("cp.async.cg.shared.global [%0], [%1], 16;\n"
                 :: "r"(dst), "l"(src));
}
__device__ __forceinline__ void cp_commit() {
    asm volatile("cp.async.commit_group;\n" ::: "memory");
}
__device__ __forceinline__ void cp_wait2() {
    asm volatile("cp.async.wait_group 2;\n" ::: "memory");
}

template<int EPI>
__global__ void __launch_bounds__(128, 2) gemm_wmma(
    const float* __restrict__ A, const float* __restrict__ B,
    const float* __restrict__ bias, const float* __restrict__ res,
    float* __restrict__ C, int M, int N, int K)
{
    extern __shared__ float smem[];

    const int tid  = threadIdx.x;
    const int w    = tid >> 5;
    const int lane = tid & 31;
    const int bm = blockIdx.y, bn = blockIdx.x;
    const int wm = w & 1;
    const int wn = w >> 1;

    const float* Abase = A + (size_t)(bm * 128) * K;
    const float* Bbase = B + (size_t)(bn * 128) * K;

    const uint32_t smem_u32 = (uint32_t)__cvta_generic_to_shared(smem);

    wmma::fragment<wmma::accumulator, 16, 16, 8, float> acc[4][4];
#pragma unroll
    for (int i = 0; i < 4; i++)
#pragma unroll
        for (int j = 0; j < 4; j++)
            wmma::fill_fragment(acc[i][j], 0.0f);

    const int KC = K >> 5;

    auto issue = [&](int c, int s) {
        const int k0 = c << 5;
        const uint32_t sbase = smem_u32 + (uint32_t)(s * 2 * STAGE_F) * 4u;
#pragma unroll
        for (int i = 0; i < 8; i++) {
            int idx = tid + i * 128, r = idx >> 3, cc = idx & 7;
            cp_async16(sbase + (uint32_t)(r * LDA + cc * 4) * 4u,
                       Abase + (size_t)r * K + k0 + cc * 4);
        }
#pragma unroll
        for (int i = 0; i < 8; i++) {
            int idx = tid + i * 128, r = idx >> 3, cc = idx & 7;
            cp_async16(sbase + (uint32_t)(STAGE_F + r * LDA + cc * 4) * 4u,
                       Bbase + (size_t)r * K + k0 + cc * 4);
        }
    };

    issue(0, 0); cp_commit();
    issue(1, 1); cp_commit();
    issue(2, 2); cp_commit();
    cp_wait2();
    __syncthreads();

    int stage = 0;
    for (int c = 0; c < KC; c++) {
        const float* Abuf = smem + stage * 2 * STAGE_F;
        const float* Bbuf = Abuf + STAGE_F;

#pragma unroll
        for (int kk = 0; kk < 32; kk += 8) {
            wmma::fragment<wmma::matrix_a, 16, 16, 8, wmma::precision::tf32,
                           wmma::row_major> af[4];
            wmma::fragment<wmma::matrix_b, 16, 16, 8, wmma::precision::tf32,
                           wmma::col_major> bf[4];
#pragma unroll
            for (int i = 0; i < 4; i++)
                wmma::load_matrix_sync(af[i], Abuf + (wm * 64 + i * 16) * LDA + kk, LDA);
#pragma unroll
            for (int j = 0; j < 4; j++)
                wmma::load_matrix_sync(bf[j], Bbuf + (wn * 64 + j * 16) * LDA + kk, LDA);
#pragma unroll
            for (int i = 0; i < 4; i++)
#pragma unroll
                for (int j = 0; j < 4; j++)
                    wmma::mma_sync(acc[i][j], af[i], bf[j], acc[i][j]);
        }

        __syncthreads();
        if (c + 3 < KC) issue(c + 3, stage);
        cp_commit();
        cp_wait2();
        __syncthreads();

        stage = (stage == 2) ? 0 : stage + 1;
    }

    float* scr = smem + w * (64 * EPI_LD);
#pragma unroll
    for (int i = 0; i < 4; i++)
#pragma unroll
        for (int j = 0; j < 4; j++)
            wmma::store_matrix_sync(scr + (i * 16) * EPI_LD + j * 16,
                                    acc[i][j], EPI_LD, wmma::mem_row_major);
    __syncwarp();

    const int gr0 = bm * 128 + wm * 64;
    const int gc0 = bn * 128 + wn * 64;
#pragma unroll
    for (int e = 0; e < 32; e++) {
        int idx = lane + e * 32;
        int r = idx >> 4, c4 = (idx & 15) << 2;
        float4 v = *(float4*)(scr + r * EPI_LD + c4);
        const size_t go = (size_t)(gr0 + r) * N + gc0 + c4;
        if (EPI == 1) {
            float4 bv = *(const float4*)(bias + gc0 + c4);
            float4 rv = *(const float4*)(res + go);
            v.x += bv.x + rv.x; v.y += bv.y + rv.y;
            v.z += bv.z + rv.z; v.w += bv.w + rv.w;
        } else if (EPI == 2) {
            float4 bv = *(const float4*)(bias + gc0 + c4);
            v.x += bv.x; v.y += bv.y; v.z += bv.z; v.w += bv.w;
            v.x = wmma::__float_to_tf32(0.5f * v.x * (1.0f + erff(v.x * 0.70710678118654752f)));
            v.y = wmma::__float_to_tf32(0.5f * v.y * (1.0f + erff(v.y * 0.70710678118654752f)));
            v.z = wmma::__float_to_tf32(0.5f * v.z * (1.0f + erff(v.z * 0.70710678118654752f)));
            v.w = wmma::__float_to_tf32(0.5f * v.w * (1.0f + erff(v.w * 0.70710678118654752f)));
        }
        *(float4*)(C + go) = v;
    }
}

// ---------------------------------------------------------------------------
// Split LayerNorm (rounds output)
// ---------------------------------------------------------------------------
__global__ void __launch_bounds__(256) ln_split_kernel(
    const float* __restrict__ x,
    const float* __restrict__ ga, const float* __restrict__ ba,
    const float* __restrict__ gb, const float* __restrict__ bb,
    const float* __restrict__ gc, const float* __restrict__ bc,
    float* __restrict__ out)
{
    __shared__ float xs[DIM];
    __shared__ float r1[256];
    __shared__ float r2[256];
    __shared__ float st_m[3];
    __shared__ float st_r[3];

    const int row = blockIdx.x;
    const int tid = threadIdx.x;
    const float* xr = x + (size_t)row * DIM;

    for (int i = tid; i < DIM; i += 256) xs[i] = xr[i];
    __syncthreads();

    const int offs[4] = {0, S1V, S2V, DIM};
    for (int s = 0; s < 3; s++) {
        const int lo = offs[s];
        const int len = offs[s + 1] - lo;
        float s1 = 0.f, s2 = 0.f;
        for (int i = tid; i < len; i += 256) {
            float v = xs[lo + i];
            s1 += v; s2 += v * v;
        }
        r1[tid] = s1; r2[tid] = s2;
        __syncthreads();
        for (int stp = 128; stp > 0; stp >>= 1) {
            if (tid < stp) { r1[tid] += r1[tid + stp]; r2[tid] += r2[tid + stp]; }
            __syncthreads();
        }
        if (tid == 0) {
            float m = r1[0] / (float)len;
            float v = r2[0] / (float)len - m * m;
            st_m[s] = m;
            st_r[s] = rsqrtf(v + EPS);
        }
        __syncthreads();
    }

    float* orow = out + (size_t)row * DIM;
    for (int i = tid; i < DIM; i += 256) {
        int s = (i < S1V) ? 0 : ((i < S2V) ? 1 : 2);
        int li = i - offs[s];
        const float* g = (s == 0) ? ga : ((s == 1) ? gb : gc);
        const float* be = (s == 0) ? ba : ((s == 1) ? bb : bc);
        float v = (xs[i] - st_m[s]) * st_r[s] * g[li] + be[li];
        orow[i] = wmma::__float_to_tf32(v);
    }
}

// ---------------------------------------------------------------------------
// Tensor-core flash attention: raw mma.m16n8k8.tf32
// Block = 128 threads (4 warps), 64 q-rows per block, 64-key tiles.
// Warp w owns q-rows [16w, 16w+16). S and P@V on HMMA; per-row online
// softmax state in registers via documented fragment layout.
// smem: qs[64][68], ks[64][68] (aliased as P after S), vs[64][72]
// ---------------------------------------------------------------------------
#define ALDK 68
#define ALDV 72
#define ATTN_SMEM ((2 * 64 * ALDK + 64 * ALDV) * 4)

__device__ __forceinline__ void mma_tf32_16x8x8(
    float d[4], uint32_t a0, uint32_t a1, uint32_t a2, uint32_t a3,
    uint32_t b0, uint32_t b1)
{
    asm volatile(
        "mma.sync.aligned.m16n8k8.row.col.f32.tf32.tf32.f32 "
        "{%0,%1,%2,%3}, {%4,%5,%6,%7}, {%8,%9}, {%0,%1,%2,%3};"
        : "+f"(d[0]), "+f"(d[1]), "+f"(d[2]), "+f"(d[3])
        : "r"(a0), "r"(a1), "r"(a2), "r"(a3), "r"(b0), "r"(b1));
}

__global__ void __launch_bounds__(128) attn_kernel(
    const float* __restrict__ qkv, float* __restrict__ y)
{
    extern __shared__ float sm[];
    float* qs = sm;                      // 64 x 68
    float* ks = sm + 64 * ALDK;          // 64 x 68 (reused for P)
    float* vs = sm + 2 * 64 * ALDK;      // 64 x 72

    const int tid  = threadIdx.x;
    const int w    = tid >> 5;
    const int lane = tid & 31;
    const int qr   = lane >> 2;          // 0..7
    const int qc   = lane & 3;           // 0..3
    const int n0 = blockIdx.x * 64;
    const int b = blockIdx.y / NHEAD;
    const int h = blockIdx.y % NHEAD;

    const float* base = qkv + (size_t)b * SEQ * (3 * DIM) + h * HD;

    // load Q tile (raw fp32; HMMA truncates to tf32)
    for (int i = tid; i < 64 * 16; i += 128) {
        int r = i >> 4, c4 = (i & 15) * 4;
        *(float4*)(qs + r * ALDK + c4) =
            *(const float4*)(base + (size_t)(n0 + r) * (3 * DIM) + c4);
    }

    float o[8][4];
    float m0 = -INFINITY, m1 = -INFINITY, l0 = 0.f, l1 = 0.f;
#pragma unroll
    for (int j = 0; j < 8; j++)
#pragma unroll
        for (int e = 0; e < 4; e++) o[j][e] = 0.f;

    const int rowA = (w * 16 + qr) * ALDK;   // this thread's P/Q row 0
    const int rowB = rowA + 8 * ALDK;        // row +8

    for (int kt = 0; kt < SEQ / 64; kt++) {
        // load K, V tiles
        for (int i = tid; i < 64 * 16; i += 128) {
            int r = i >> 4, c4 = (i & 15) * 4;
            const float* kp = base + DIM + (size_t)(kt * 64 + r) * (3 * DIM) + c4;
            *(float4*)(ks + r * ALDK + c4) = *(const float4*)kp;
            *(float4*)(vs + r * ALDV + c4) = *(const float4*)(kp + DIM);
        }
        __syncthreads();

        // ---- S = Q @ K^T : s[j] = 16x8 tile over keys [8j, 8j+8)
        float s[8][4];
#pragma unroll
        for (int j = 0; j < 8; j++)
#pragma unroll
            for (int e = 0; e < 4; e++) s[j][e] = 0.f;

#pragma unroll
        for (int k8 = 0; k8 < 8; k8++) {
            const int kb = k8 * 8;
            uint32_t a0 = __float_as_uint(qs[rowA + kb + qc]);
            uint32_t a1 = __float_as_uint(qs[rowB + kb + qc]);
            uint32_t a2 = __float_as_uint(qs[rowA + kb + qc + 4]);
            uint32_t a3 = __float_as_uint(qs[rowB + kb + qc + 4]);
#pragma unroll
            for (int j = 0; j < 8; j++) {
                // B[k][n] = K[n][k]: ks[(8j+qr)][kb+qc]
                uint32_t b0 = __float_as_uint(ks[(j * 8 + qr) * ALDK + kb + qc]);
                uint32_t b1 = __float_as_uint(ks[(j * 8 + qr) * ALDK + kb + qc + 4]);
                mma_tf32_16x8x8(s[j], a0, a1, a2, a3, b0, b1);
            }
        }
        __syncthreads();   // all warps done reading ks -> safe to write P

        // ---- online softmax (rows r0 = w*16+qr, r1 = r0+8)
        float mx0 = -INFINITY, mx1 = -INFINITY;
#pragma unroll
        for (int j = 0; j < 8; j++) {
#pragma unroll
            for (int e = 0; e < 4; e++) s[j][e] *= SCALE;
            mx0 = fmaxf(mx0, fmaxf(s[j][0], s[j][1]));
            mx1 = fmaxf(mx1, fmaxf(s[j][2], s[j][3]));
        }
        mx0 = fmaxf(mx0, __shfl_xor_sync(0xffffffffu, mx0, 1));
        mx0 = fmaxf(mx0, __shfl_xor_sync(0xffffffffu, mx0, 2));
        mx1 = fmaxf(mx1, __shfl_xor_sync(0xffffffffu, mx1, 1));
        mx1 = fmaxf(mx1, __shfl_xor_sync(0xffffffffu, mx1, 2));

        float mn0 = fmaxf(m0, mx0), mn1 = fmaxf(m1, mx1);
        float c0 = __expf(m0 - mn0), c1 = __expf(m1 - mn1);
        float rs0 = 0.f, rs1 = 0.f;

#pragma unroll
        for (int j = 0; j < 8; j++) {
            float p0 = __expf(s[j][0] - mn0);
            float p1 = __expf(s[j][1] - mn0);
            float p2 = __expf(s[j][2] - mn1);
            float p3 = __expf(s[j][3] - mn1);
            rs0 += p0 + p1; rs1 += p2 + p3;
            // store P into ks (reused): row-major [64][ALDK]
            float* pr0 = ks + rowA + j * 8 + qc * 2;
            float* pr1 = ks + rowB + j * 8 + qc * 2;
            pr0[0] = p0; pr0[1] = p1;
            pr1[0] = p2; pr1[1] = p3;
            // rescale O
            o[j][0] *= c0; o[j][1] *= c0; o[j][2] *= c1; o[j][3] *= c1;
        }
        rs0 += __shfl_xor_sync(0xffffffffu, rs0, 1);
        rs0 += __shfl_xor_sync(0xffffffffu, rs0, 2);
        rs1 += __shfl_xor_sync(0xffffffffu, rs1, 1);
        rs1 += __shfl_xor_sync(0xffffffffu, rs1, 2);
        l0 = l0 * c0 + rs0; l1 = l1 * c1 + rs1;
        m0 = mn0; m1 = mn1;
        __syncwarp();      // warp's own P rows visible (PV reads only own rows)

        // ---- O += P @ V : o[j] = 16x8 tile over headdim [8j, 8j+8)
#pragma unroll
        for (int k8 = 0; k8 < 8; k8++) {
            const int kb = k8 * 8;
            uint32_t a0 = __float_as_uint(ks[rowA + kb + qc]);
            uint32_t a1 = __float_as_uint(ks[rowB + kb + qc]);
            uint32_t a2 = __float_as_uint(ks[rowA + kb + qc + 4]);
            uint32_t a3 = __float_as_uint(ks[rowB + kb + qc + 4]);
#pragma unroll
            for (int j = 0; j < 8; j++) {
                // B[k][n] = V[k][n]: vs[kb+qc][8j+qr]
                uint32_t b0 = __float_as_uint(vs[(kb + qc) * ALDV + j * 8 + qr]);
                uint32_t b1 = __float_as_uint(vs[(kb + qc + 4) * ALDV + j * 8 + qr]);
                mma_tf32_16x8x8(o[j], a0, a1, a2, a3, b0, b1);
            }
        }
        __syncthreads();   // done with ks(P) and vs before next tile load
    }

    // ---- write y (rounded to tf32: feeds proj GEMM A operand)
    const float i0 = 1.0f / l0, i1 = 1.0f / l1;
    const int gr0 = b * SEQ + n0 + w * 16 + qr;
    float* y0 = y + (size_t)gr0 * DIM + h * HD;
    float* y1 = y0 + (size_t)8 * DIM;
#pragma unroll
    for (int j = 0; j < 8; j++) {
        const int cb = j * 8 + qc * 2;
        y0[cb]     = wmma::__float_to_tf32(o[j][0] * i0);
        y0[cb + 1] = wmma::__float_to_tf32(o[j][1] * i0);
        y1[cb]     = wmma::__float_to_tf32(o[j][2] * i1);
        y1[cb + 1] = wmma::__float_to_tf32(o[j][3] * i1);
    }
}

// ---------------------------------------------------------------------------
// Launch
// ---------------------------------------------------------------------------
extern "C" void kernel_launch(void* const* d_in, const int* in_sizes, int n_in,
                              void* d_out, int out_size)
{
    const float* x      = (const float*)d_in[0];
    const float* ln1a_g = (const float*)d_in[1];
    const float* ln1a_b = (const float*)d_in[2];
    const float* ln1b_g = (const float*)d_in[3];
    const float* ln1b_b = (const float*)d_in[4];
    const float* ln1c_g = (const float*)d_in[5];
    const float* ln1c_b = (const float*)d_in[6];
    const float* ln2a_g = (const float*)d_in[7];
    const float* ln2a_b = (const float*)d_in[8];
    const float* ln2b_g = (const float*)d_in[9];
    const float* ln2b_b = (const float*)d_in[10];
    const float* ln2c_g = (const float*)d_in[11];
    const float* ln2c_b = (const float*)d_in[12];
    const float* qkv_w  = (const float*)d_in[13];
    const float* proj_w = (const float*)d_in[14];
    const float* proj_b = (const float*)d_in[15];
    const float* fc1_w  = (const float*)d_in[16];
    const float* fc1_b  = (const float*)d_in[17];
    const float* fc2_w  = (const float*)d_in[18];
    const float* fc2_b  = (const float*)d_in[19];
    float* out = (float*)d_out;

    float *p_normx, *p_qkv, *p_y, *p_h, *p_wq, *p_wp, *p_w1, *p_w2;
    cudaGetSymbolAddress((void**)&p_normx, g_normx);
    cudaGetSymbolAddress((void**)&p_qkv,   g_qkv);
    cudaGetSymbolAddress((void**)&p_y,     g_y);
    cudaGetSymbolAddress((void**)&p_h,     g_h);
    cudaGetSymbolAddress((void**)&p_wq,    g_wq);
    cudaGetSymbolAddress((void**)&p_wp,    g_wp);
    cudaGetSymbolAddress((void**)&p_w1,    g_w1);
    cudaGetSymbolAddress((void**)&p_w2,    g_w2);

    cudaFuncSetAttribute(attn_kernel,
                         cudaFuncAttributeMaxDynamicSharedMemorySize, ATTN_SMEM);
    cudaFuncSetAttribute(gemm_wmma<0>,
                         cudaFuncAttributeMaxDynamicSharedMemorySize, GEMM_SMEM);
    cudaFuncSetAttribute(gemm_wmma<1>,
                         cudaFuncAttributeMaxDynamicSharedMemorySize, GEMM_SMEM);
    cudaFuncSetAttribute(gemm_wmma<2>,
                         cudaFuncAttributeMaxDynamicSharedMemorySize, GEMM_SMEM);

    // 0. round weights to tf32 (RN)
    {
        int n;
        n = 3 * DIM * DIM / 4;
        round_tf32_kernel<<<(n + 255) / 256, 256>>>(qkv_w, p_wq, n);
        n = DIM * DIM / 4;
        round_tf32_kernel<<<(n + 255) / 256, 256>>>(proj_w, p_wp, n);
        n = HID * DIM / 4;
        round_tf32_kernel<<<(n + 255) / 256, 256>>>(fc1_w, p_w1, n);
        n = DIM * HID / 4;
        round_tf32_kernel<<<(n + 255) / 256, 256>>>(fc2_w, p_w2, n);
    }

    // 1. norm1
    ln_split_kernel<<<TOK, 256>>>(x, ln1a_g, ln1a_b, ln1b_g, ln1b_b,
                                  ln1c_g, ln1c_b, p_normx);

    // 2. QKV
    gemm_wmma<0><<<dim3(3 * DIM / 128, TOK / 128), 128, GEMM_SMEM>>>(
        p_normx, p_wq, nullptr, nullptr, p_qkv, TOK, 3 * DIM, DIM);

    // 3. attention (tensor-core)
    attn_kernel<<<dim3(SEQ / 64, BATCH * NHEAD), 128, ATTN_SMEM>>>(p_qkv, p_y);

    // 4. proj + bias + residual(x)
    gemm_wmma<1><<<dim3(DIM / 128, TOK / 128), 128, GEMM_SMEM>>>(
        p_y, p_wp, proj_b, x, out, TOK, DIM, DIM);

    // 5. norm2
    ln_split_kernel<<<TOK, 256>>>(out, ln2a_g, ln2a_b, ln2b_g, ln2b_b,
                                  ln2c_g, ln2c_b, p_normx);

    // 6. FC1 + bias + GELU
    gemm_wmma<2><<<dim3(HID / 128, TOK / 128), 128, GEMM_SMEM>>>(
        p_normx, p_w1, fc1_b, nullptr, p_h, TOK, HID, DIM);

    // 7. FC2 + bias + residual(out)
    gemm_wmma<1><<<dim3(DIM / 128, TOK / 128), 128, GEMM_SMEM>>>(
        p_h, p_w2, fc2_b, out, out, TOK, DIM, HID);
}